// round 1
// baseline (speedup 1.0000x reference)
#include <cuda_runtime.h>
#include <math.h>
#include <float.h>

// Problem constants (validated against in_sizes at launch).
#define MAXN 50000
#define MAXE 800000
#define DMAX 256

// ---------------- static device scratch (no allocations allowed) ----------------
__device__ float g_q[(size_t)MAXN * DMAX];
__device__ float g_k[(size_t)MAXN * DMAX];
__device__ float g_v[(size_t)MAXN * DMAX];
__device__ float g_h1[(size_t)MAXN * DMAX];
__device__ float g_h2[(size_t)MAXN * DMAX];
__device__ float g_score[MAXE];
__device__ float g_denom[MAXN];
__device__ unsigned g_smax[MAXN];
__device__ int g_src[MAXE];
__device__ int g_dst[MAXE];
__device__ int g_is64;
__device__ float g_psum[256];
__device__ unsigned g_pmax[256];

__device__ __forceinline__ float* sel(int w) {
    switch (w) {
        case 0: return g_q;
        case 1: return g_k;
        case 2: return g_v;
        case 3: return g_h1;
        default: return g_h2;
    }
}

// Order-preserving float<->uint encoding for atomicMax on floats.
__device__ __forceinline__ unsigned fenc(float f) {
    unsigned u = __float_as_uint(f);
    return (u & 0x80000000u) ? ~u : (u | 0x80000000u);
}
__device__ __forceinline__ float fdec(unsigned u) {
    u = (u & 0x80000000u) ? (u ^ 0x80000000u) : ~u;
    return __uint_as_float(u);
}
#define ENC_NEG_INF 0x007FFFFFu   // fenc(-inf)

// ---------------- edge index width detection + conversion ----------------
__global__ void detect_kernel(const unsigned* __restrict__ ei, int E) {
    if (threadIdx.x == 0 && blockIdx.x == 0) {
        int n = E < 64 ? E : 64;
        int is64 = 1;
        for (int i = 0; i < n; i++) {
            if (ei[2 * i + 1] != 0u) { is64 = 0; break; }
        }
        g_is64 = is64;
    }
}

__global__ void convert_kernel(const void* __restrict__ ei, int E) {
    int i = blockIdx.x * blockDim.x + threadIdx.x;
    if (i >= E) return;
    if (g_is64) {
        const long long* p = (const long long*)ei;
        g_src[i] = (int)p[i];
        g_dst[i] = (int)p[E + i];
    } else {
        const int* p = (const int*)ei;
        g_src[i] = p[i];
        g_dst[i] = p[E + i];
    }
}

// ---------------- fp32 tiled GEMM: C = A @ W + bias ----------------
#define BM 64
#define BN 64
#define BK 16
__global__ void gemm_bias_kernel(const float* __restrict__ Aext, int a_sel,
                                 const float* __restrict__ W,
                                 const float* __restrict__ bias,
                                 int c_sel, int M, int K, int N, int sanitize) {
    __shared__ float As[BK][BM];
    __shared__ float Ws[BK][BN];
    const float* A = (a_sel >= 0) ? sel(a_sel) : Aext;
    float* C = sel(c_sel);

    int tid = threadIdx.x;          // 256 threads
    int tx = tid & 15;              // 0..15 (N direction, 4 cols each)
    int ty = tid >> 4;              // 0..15 (M direction, 4 rows each)
    int rowBase = blockIdx.y * BM;
    int colBase = blockIdx.x * BN;

    float acc[4][4];
#pragma unroll
    for (int i = 0; i < 4; i++)
#pragma unroll
        for (int j = 0; j < 4; j++) acc[i][j] = 0.f;

    for (int k0 = 0; k0 < K; k0 += BK) {
        // A tile 64x16 -> As[k][m]
#pragma unroll
        for (int i = 0; i < 4; i++) {
            int idx = tid + i * 256;
            int m = idx >> 4, kk = idx & 15;
            int gr = rowBase + m;
            float v = 0.f;
            if (gr < M) v = A[(size_t)gr * K + k0 + kk];
            if (sanitize && (v != v)) v = 0.f;   // nan_to_num
            As[kk][m] = v;
        }
        // W tile 16x64 -> Ws[k][n]
#pragma unroll
        for (int i = 0; i < 4; i++) {
            int idx = tid + i * 256;
            int kk = idx >> 6, nn = idx & 63;
            Ws[kk][nn] = W[(size_t)(k0 + kk) * N + colBase + nn];
        }
        __syncthreads();
#pragma unroll
        for (int kk = 0; kk < BK; kk++) {
            float a[4], w[4];
#pragma unroll
            for (int i = 0; i < 4; i++) a[i] = As[kk][ty * 4 + i];
#pragma unroll
            for (int j = 0; j < 4; j++) w[j] = Ws[kk][tx * 4 + j];
#pragma unroll
            for (int i = 0; i < 4; i++)
#pragma unroll
                for (int j = 0; j < 4; j++) acc[i][j] += a[i] * w[j];
        }
        __syncthreads();
    }

#pragma unroll
    for (int i = 0; i < 4; i++) {
        int gr = rowBase + ty * 4 + i;
        if (gr >= M) continue;
#pragma unroll
        for (int j = 0; j < 4; j++) {
            int gc = colBase + tx * 4 + j;
            C[(size_t)gr * N + gc] = acc[i][j] + bias[gc];
        }
    }
}

// ---------------- per-node softmax-state init ----------------
__global__ void init_nodes_kernel(int Nn) {
    int i = blockIdx.x * blockDim.x + threadIdx.x;
    if (i < Nn) {
        g_smax[i] = ENC_NEG_INF;
        g_denom[i] = 0.f;
    }
}

// ---------------- edge score: score[e] = q[dst].k[src] / sqrt(d), track segment max ----------------
__global__ void edge_score_kernel(int E, int d, float inv_sqrt_d) {
    int e = (blockIdx.x * blockDim.x + threadIdx.x) >> 5;
    int lane = threadIdx.x & 31;
    if (e >= E) return;
    int s = g_src[e], t = g_dst[e];
    const float* qr = g_q + (size_t)t * d;
    const float* kr = g_k + (size_t)s * d;
    float sum = 0.f;
    for (int j = lane * 4; j < d; j += 128) {
        float4 a = *(const float4*)(qr + j);
        float4 b = *(const float4*)(kr + j);
        sum += a.x * b.x + a.y * b.y + a.z * b.z + a.w * b.w;
    }
#pragma unroll
    for (int o = 16; o; o >>= 1) sum += __shfl_xor_sync(0xFFFFFFFFu, sum, o);
    if (lane == 0) {
        float sc = sum * inv_sqrt_d;
        g_score[e] = sc;
        atomicMax(&g_smax[t], fenc(sc));
    }
}

// ---------------- exp + denominator ----------------
__global__ void edge_exp_kernel(int E) {
    int e = blockIdx.x * blockDim.x + threadIdx.x;
    if (e >= E) return;
    int t = g_dst[e];
    float ex = expf(g_score[e] - fdec(g_smax[t]));
    g_score[e] = ex;
    atomicAdd(&g_denom[t], ex);
}

// ---------------- scatter: h[dst] += alpha * v[src] ----------------
__global__ void edge_scatter_kernel(int E, int d, int h_sel) {
    int e = (blockIdx.x * blockDim.x + threadIdx.x) >> 5;
    int lane = threadIdx.x & 31;
    if (e >= E) return;
    int s = g_src[e], t = g_dst[e];
    float alpha = g_score[e] / g_denom[t];
    const float* vr = g_v + (size_t)s * d;
    float* hr = sel(h_sel) + (size_t)t * d;
    for (int j = lane * 4; j < d; j += 128) {
        float4 a = *(const float4*)(vr + j);
        atomicAdd(&hr[j + 0], alpha * a.x);
        atomicAdd(&hr[j + 1], alpha * a.y);
        atomicAdd(&hr[j + 2], alpha * a.z);
        atomicAdd(&hr[j + 3], alpha * a.w);
    }
}

// ---------------- pooling ----------------
__global__ void pool_init_kernel() {
    int c = threadIdx.x;
    if (c < 256) {
        g_psum[c] = 0.f;
        g_pmax[c] = ENC_NEG_INF;
    }
}

__global__ void pool_kernel(int M, int d) {
    int c = threadIdx.x;   // 0..d-1
    const float* h = g_h2;
    float sum = 0.f, mx = -FLT_MAX;
    for (int r = blockIdx.x; r < M; r += gridDim.x) {
        float v = h[(size_t)r * d + c];
        sum += v;
        mx = fmaxf(mx, v);
    }
    atomicAdd(&g_psum[c], sum);
    atomicMax(&g_pmax[c], fenc(mx));
}

__global__ void pool_final_kernel(float* __restrict__ out, int M, int d) {
    int c = threadIdx.x;
    if (c < d) {
        out[c] = g_psum[c] / (float)M;
        out[d + c] = fdec(g_pmax[c]);
    }
}

// ---------------- launch ----------------
extern "C" void kernel_launch(void* const* d_in, const int* in_sizes, int n_in,
                              void* d_out, int out_size) {
    const float* x   = (const float*)d_in[0];
    const void*  ei  = d_in[1];
    // d_in[2] = edge_weight (unused by the reference)
    const float* Wq1 = (const float*)d_in[3];
    const float* bq1 = (const float*)d_in[4];
    const float* Wk1 = (const float*)d_in[5];
    const float* bk1 = (const float*)d_in[6];
    const float* Wv1 = (const float*)d_in[7];
    const float* bv1 = (const float*)d_in[8];
    const float* Ws1 = (const float*)d_in[9];
    const float* bs1 = (const float*)d_in[10];
    const float* Wq2 = (const float*)d_in[11];
    const float* bq2 = (const float*)d_in[12];
    const float* Wk2 = (const float*)d_in[13];
    const float* bk2 = (const float*)d_in[14];
    const float* Wv2 = (const float*)d_in[15];
    const float* bv2 = (const float*)d_in[16];
    const float* Ws2 = (const float*)d_in[17];
    const float* bs2 = (const float*)d_in[18];
    float* out = (float*)d_out;

    const int D_IN = 512, D_HID = 256, D_OUT = 128;
    int Nn = in_sizes[0] / D_IN;    // 50000
    int E  = in_sizes[2];           // 800000

    // edge index conversion
    detect_kernel<<<1, 32>>>((const unsigned*)ei, E);
    convert_kernel<<<(E + 255) / 256, 256>>>(ei, E);

    dim3 gemmBlk(256);
    int gy = (Nn + BM - 1) / BM;

    // ===== layer 1 (input x, sanitize NaN; K=512, N=256) =====
    {
        dim3 g(D_HID / BN, gy);
        gemm_bias_kernel<<<g, gemmBlk>>>(x, -1, Wq1, bq1, 0, Nn, D_IN, D_HID, 1);
        gemm_bias_kernel<<<g, gemmBlk>>>(x, -1, Wk1, bk1, 1, Nn, D_IN, D_HID, 1);
        gemm_bias_kernel<<<g, gemmBlk>>>(x, -1, Wv1, bv1, 2, Nn, D_IN, D_HID, 1);
        gemm_bias_kernel<<<g, gemmBlk>>>(x, -1, Ws1, bs1, 3, Nn, D_IN, D_HID, 1);
    }
    init_nodes_kernel<<<(Nn + 255) / 256, 256>>>(Nn);
    {
        float inv = (float)(1.0 / sqrt((double)D_HID));
        int warpsPerBlk = 8;
        int blks = (E + warpsPerBlk - 1) / warpsPerBlk;
        edge_score_kernel<<<blks, 256>>>(E, D_HID, inv);
        edge_exp_kernel<<<(E + 255) / 256, 256>>>(E);
        edge_scatter_kernel<<<blks, 256>>>(E, D_HID, 3);   // into g_h1 (already holds skip)
    }

    // ===== layer 2 (input g_h1; K=256, N=128) =====
    {
        dim3 g(D_OUT / BN, gy);
        gemm_bias_kernel<<<g, gemmBlk>>>(nullptr, 3, Wq2, bq2, 0, Nn, D_HID, D_OUT, 0);
        gemm_bias_kernel<<<g, gemmBlk>>>(nullptr, 3, Wk2, bk2, 1, Nn, D_HID, D_OUT, 0);
        gemm_bias_kernel<<<g, gemmBlk>>>(nullptr, 3, Wv2, bv2, 2, Nn, D_HID, D_OUT, 0);
        gemm_bias_kernel<<<g, gemmBlk>>>(nullptr, 3, Ws2, bs2, 4, Nn, D_HID, D_OUT, 0);
    }
    init_nodes_kernel<<<(Nn + 255) / 256, 256>>>(Nn);
    {
        float inv = (float)(1.0 / sqrt((double)D_OUT));
        int warpsPerBlk = 8;
        int blks = (E + warpsPerBlk - 1) / warpsPerBlk;
        edge_score_kernel<<<blks, 256>>>(E, D_OUT, inv);
        edge_exp_kernel<<<(E + 255) / 256, 256>>>(E);
        edge_scatter_kernel<<<blks, 256>>>(E, D_OUT, 4);   // into g_h2 (already holds skip)
    }

    // ===== pooling =====
    pool_init_kernel<<<1, 256>>>();
    pool_kernel<<<256, D_OUT>>>(Nn, D_OUT);
    pool_final_kernel<<<1, 256>>>(out, Nn, D_OUT);
}